// round 2
// baseline (speedup 1.0000x reference)
#include <cuda_runtime.h>

// ---------------- problem constants ----------------
// B=2, C=21, H=W=512, pooled 128x128, K=11 (radius 5), 5 steps, pad=(0,0)

// ---------------- scratch (device globals; no mallocs allowed) ----------------
__device__ float g_unary[11010048];   // [2][21][512][512]
__device__ float g_qb[688128];        // [2][21][128][128]
__device__ float g_msg[688128];       // [2][21][128][128]
__device__ float g_kcomb[3964928];    // [2][121][128][128]  (j-major)
__device__ float g_rgbp[98304];       // [2][3][128][128]    (already /13)

// ---------------- backbone 3x3 conv, 3 -> 21 ----------------
__global__ void k_conv(const float* __restrict__ x, const float* __restrict__ w,
                       const float* __restrict__ bias) {
  __shared__ float xs[3][10][34];
  __shared__ float ws[567];
  __shared__ float bs[21];
  const int b  = blockIdx.z;
  const int x0 = blockIdx.x * 32, y0 = blockIdx.y * 8;
  const int tx = threadIdx.x, ty = threadIdx.y;
  const int tid = ty * 32 + tx;
  for (int i = tid; i < 567; i += 256) ws[i] = w[i];
  if (tid < 21) bs[tid] = bias[tid];
  for (int i = tid; i < 3 * 10 * 34; i += 256) {
    int c = i / 340, rem = i % 340, yy = rem / 34, xx = rem % 34;
    int gy = y0 + yy - 1, gx = x0 + xx - 1;
    float v = 0.f;
    if (gy >= 0 && gy < 512 && gx >= 0 && gx < 512)
      v = x[((size_t)(b * 3 + c) << 18) + (gy << 9) + gx];
    xs[c][yy][xx] = v;
  }
  __syncthreads();
  float r[27];
#pragma unroll
  for (int c = 0; c < 3; c++)
#pragma unroll
    for (int ky = 0; ky < 3; ky++)
#pragma unroll
      for (int kx = 0; kx < 3; kx++)
        r[c * 9 + ky * 3 + kx] = xs[c][ty + ky][tx + kx];
  float* outp = g_unary + ((size_t)b * 21 << 18) + ((y0 + ty) << 9) + (x0 + tx);
#pragma unroll
  for (int o = 0; o < 21; o++) {
    float acc = bs[o];
#pragma unroll
    for (int i = 0; i < 27; i++) acc = fmaf(r[i], ws[o * 27 + i], acc);
    outp[(size_t)o << 18] = acc;
  }
}

// ---------------- 4x4 avg-pool of x, folded /13 ----------------
__global__ void k_poolrgb(const float* __restrict__ x) {
  int idx = blockIdx.x * 256 + threadIdx.x;  // over 2*3*128*128
  if (idx >= 98304) return;
  int xp = idx & 127, yp = (idx >> 7) & 127, c = idx >> 14;  // c = b*3+ch
  const float* p = x + ((size_t)c << 18) + ((yp * 4) << 9) + (xp * 4);
  float s = 0.f;
#pragma unroll
  for (int i = 0; i < 4; i++)
#pragma unroll
    for (int j = 0; j < 4; j++) s += p[(i << 9) + j];
  g_rgbp[idx] = s * (1.0f / 208.0f);  // /16 pool, /13 feature scale
}

// ---------------- combined pairwise kernel: w1*bilateral + w2*spatial ----------------
__global__ void k_kernels(const float* __restrict__ pw) {
  __shared__ float rs[3][18][42];
  __shared__ float sA[121], sS[121];
  const int b  = blockIdx.z;
  const int x0 = blockIdx.x * 32, y0 = blockIdx.y * 8;
  const int tx = threadIdx.x, ty = threadIdx.y;
  const int tid = ty * 32 + tx;
  if (tid < 121) {
    int dy = tid / 11 - 5, dx = tid % 11 - 5;
    float d2 = (float)(dy * dy + dx * dx);
    sA[tid] = __expf(-d2 * (1.0f / 800.0f));  // pooled YX/80: (4d/80)^2/2
    sS[tid] = __expf(-d2 * (8.0f / 9.0f));    // pooled YX/3 : (4d/3)^2/2
  }
  for (int i = tid; i < 3 * 18 * 42; i += 256) {
    int c = i / 756, rem = i % 756, yy = rem / 42, xx = rem % 42;
    int gy = y0 + yy - 5, gx = x0 + xx - 5;
    float v = 0.f;
    if (gy >= 0 && gy < 128 && gx >= 0 && gx < 128)
      v = g_rgbp[((b * 3 + c) << 14) + (gy << 7) + gx];
    rs[c][yy][xx] = v;
  }
  __syncthreads();
  const float w1 = pw[0], w2 = pw[1];
  const float r0 = rs[0][ty + 5][tx + 5];
  const float r1 = rs[1][ty + 5][tx + 5];
  const float r2 = rs[2][ty + 5][tx + 5];
  const int y = y0 + ty, xg = x0 + tx;
  float* outp = g_kcomb + ((size_t)b * 121 << 14) + (y << 7) + xg;
  for (int dy = 0; dy < 11; dy++) {
    for (int dx = 0; dx < 11; dx++) {
      int j = dy * 11 + dx;
      int ny = y + dy - 5, nx = xg + dx - 5;
      float val = 0.f;  // OOB entries multiply zero-padded Q patches -> store 0
      if (ny >= 0 && ny < 128 && nx >= 0 && nx < 128) {
        float a = rs[0][ty + dy][tx + dx] - r0;
        float bb = rs[1][ty + dy][tx + dx] - r1;
        float cc = rs[2][ty + dy][tx + dx] - r2;
        float d2 = a * a + bb * bb + cc * cc;
        val = fmaf(w1 * sA[j], __expf(-0.5f * d2), w2 * sS[j]);
      }
      outp[(size_t)j << 14] = val;
    }
  }
}

// ---------------- fused: (uw*unary + upsample(msg)) -> softmax -> 4x4 pool ----------------
template <bool HAS_MSG>
__global__ void k_softpool(const float* __restrict__ uwp) {
  __shared__ float ms[21][10][10];
  const int b  = blockIdx.z;
  const int x0 = blockIdx.x * 32, y0 = blockIdx.y * 32;
  const int tx = threadIdx.x, ty = threadIdx.y;
  const int tid = ty * 32 + tx;
  const float uw = uwp[0];
  if (HAS_MSG) {
    int qx0 = (x0 >> 2) - 1, qy0 = (y0 >> 2) - 1;
    for (int i = tid; i < 2100; i += 256) {
      int c = i / 100, rem = i % 100, yy = rem / 10, xx = rem % 10;
      int gy = min(max(qy0 + yy, 0), 127), gx = min(max(qx0 + xx, 0), 127);
      ms[c][yy][xx] = g_msg[((b * 21 + c) << 14) + (gy << 7) + gx];
    }
    __syncthreads();
  }
  const int xg = x0 + tx;
  const int rx = tx & 3, lqx = (tx >> 2) + 1;
  int ix0; float wx0;
  if (rx == 0)      { ix0 = lqx - 1; wx0 = 0.375f; }
  else if (rx == 1) { ix0 = lqx - 1; wx0 = 0.125f; }
  else if (rx == 2) { ix0 = lqx;     wx0 = 0.875f; }
  else              { ix0 = lqx;     wx0 = 0.625f; }
  const float wx1 = 1.f - wx0;
  float qacc[21];
#pragma unroll
  for (int c = 0; c < 21; c++) qacc[c] = 0.f;
#pragma unroll
  for (int k = 0; k < 4; k++) {
    const int y = y0 + ty * 4 + k;
    const int lqy = ty + 1;
    int iy0; float wy0;
    if (k == 0)      { iy0 = lqy - 1; wy0 = 0.375f; }
    else if (k == 1) { iy0 = lqy - 1; wy0 = 0.125f; }
    else if (k == 2) { iy0 = lqy;     wy0 = 0.875f; }
    else             { iy0 = lqy;     wy0 = 0.625f; }
    const float wy1 = 1.f - wy0;
    const float* up = g_unary + ((size_t)b * 21 << 18) + (y << 9) + xg;
    float logit[21];
    float mx = -1e30f;
#pragma unroll
    for (int c = 0; c < 21; c++) {
      float v = uw * up[(size_t)c << 18];
      if (HAS_MSG) {
        float a  = wx0 * ms[c][iy0][ix0]     + wx1 * ms[c][iy0][ix0 + 1];
        float bb = wx0 * ms[c][iy0 + 1][ix0] + wx1 * ms[c][iy0 + 1][ix0 + 1];
        v += wy0 * a + wy1 * bb;
      }
      logit[c] = v;
      mx = fmaxf(mx, v);
    }
    float s = 0.f;
#pragma unroll
    for (int c = 0; c < 21; c++) { float e = __expf(logit[c] - mx); logit[c] = e; s += e; }
    float inv = __frcp_rn(s);
#pragma unroll
    for (int c = 0; c < 21; c++) qacc[c] = fmaf(logit[c], inv, qacc[c]);
  }
  // reduce 4 adjacent x-columns (warp = one ty row of 32 lanes)
#pragma unroll
  for (int c = 0; c < 21; c++) {
    qacc[c] += __shfl_down_sync(0xffffffffu, qacc[c], 1);
    qacc[c] += __shfl_down_sync(0xffffffffu, qacc[c], 2);
  }
  if ((tx & 3) == 0) {
    const int yp = (y0 >> 2) + ty, xp = (x0 >> 2) + (tx >> 2);
#pragma unroll
    for (int c = 0; c < 21; c++)
      g_qb[((b * 21 + c) << 14) + (yp << 7) + xp] = qacc[c] * 0.0625f;
  }
}

// ---------------- pixel-adaptive 11x11 message at 128x128 ----------------
__global__ void k_pac() {
  __shared__ float qs[21][18][26];  // 16x8 tile + radius-5 halo, zero-padded
  const int b  = blockIdx.z;
  const int x0 = blockIdx.x * 16, y0 = blockIdx.y * 8;
  const int tx = threadIdx.x, ty = threadIdx.y;
  const int tid = ty * 16 + tx;  // 128 threads
  for (int i = tid; i < 21 * 18 * 26; i += 128) {
    int c = i / 468, rem = i % 468, yy = rem / 26, xx = rem % 26;
    int gy = y0 + yy - 5, gx = x0 + xx - 5;
    float v = 0.f;
    if (gy >= 0 && gy < 128 && gx >= 0 && gx < 128)
      v = g_qb[((b * 21 + c) << 14) + (gy << 7) + gx];
    qs[c][yy][xx] = v;
  }
  __syncthreads();
  float acc[21];
#pragma unroll
  for (int c = 0; c < 21; c++) acc[c] = 0.f;
  const int y = y0 + ty, xg = x0 + tx;
  const float* kp = g_kcomb + ((size_t)b * 121 << 14) + (y << 7) + xg;
  for (int dy = 0; dy < 11; dy++) {
    for (int dx = 0; dx < 11; dx++) {
      float kv = __ldg(kp + ((size_t)(dy * 11 + dx) << 14));
      const float* q = &qs[0][ty + dy][tx + dx];
#pragma unroll
      for (int c = 0; c < 21; c++) acc[c] = fmaf(kv, q[c * 468], acc[c]);
    }
  }
  float* mp = g_msg + ((size_t)b * 21 << 14) + (y << 7) + xg;
#pragma unroll
  for (int c = 0; c < 21; c++) mp[(size_t)c << 14] = acc[c];
}

// ---------------- last step: logQ = uw*unary + upsample(msg) -> d_out ----------------
__global__ void k_final(const float* __restrict__ uwp, float* __restrict__ out) {
  __shared__ float ms[21][10][10];
  const int b  = blockIdx.z;
  const int x0 = blockIdx.x * 32, y0 = blockIdx.y * 32;
  const int tx = threadIdx.x, ty = threadIdx.y;
  const int tid = ty * 32 + tx;
  const float uw = uwp[0];
  {
    int qx0 = (x0 >> 2) - 1, qy0 = (y0 >> 2) - 1;
    for (int i = tid; i < 2100; i += 256) {
      int c = i / 100, rem = i % 100, yy = rem / 10, xx = rem % 10;
      int gy = min(max(qy0 + yy, 0), 127), gx = min(max(qx0 + xx, 0), 127);
      ms[c][yy][xx] = g_msg[((b * 21 + c) << 14) + (gy << 7) + gx];
    }
    __syncthreads();
  }
  const int xg = x0 + tx;
  const int rx = tx & 3, lqx = (tx >> 2) + 1;
  int ix0; float wx0;
  if (rx == 0)      { ix0 = lqx - 1; wx0 = 0.375f; }
  else if (rx == 1) { ix0 = lqx - 1; wx0 = 0.125f; }
  else if (rx == 2) { ix0 = lqx;     wx0 = 0.875f; }
  else              { ix0 = lqx;     wx0 = 0.625f; }
  const float wx1 = 1.f - wx0;
#pragma unroll
  for (int k = 0; k < 4; k++) {
    const int y = y0 + ty * 4 + k;
    const int lqy = ty + 1;
    int iy0; float wy0;
    if (k == 0)      { iy0 = lqy - 1; wy0 = 0.375f; }
    else if (k == 1) { iy0 = lqy - 1; wy0 = 0.125f; }
    else if (k == 2) { iy0 = lqy;     wy0 = 0.875f; }
    else             { iy0 = lqy;     wy0 = 0.625f; }
    const float wy1 = 1.f - wy0;
    const float* up = g_unary + ((size_t)b * 21 << 18) + (y << 9) + xg;
    float* op = out + ((size_t)b * 21 << 18) + (y << 9) + xg;
#pragma unroll
    for (int c = 0; c < 21; c++) {
      float v = uw * up[(size_t)c << 18];
      float a  = wx0 * ms[c][iy0][ix0]     + wx1 * ms[c][iy0][ix0 + 1];
      float bb = wx0 * ms[c][iy0 + 1][ix0] + wx1 * ms[c][iy0 + 1][ix0 + 1];
      op[(size_t)c << 18] = v + wy0 * a + wy1 * bb;
    }
  }
}

extern "C" void kernel_launch(void* const* d_in, const int* in_sizes, int n_in,
                              void* d_out, int out_size) {
  const float* x    = (const float*)d_in[0];
  const float* w    = (const float*)d_in[1];
  const float* bias = (const float*)d_in[2];
  const float* uw   = (const float*)d_in[3];
  const float* pw   = (const float*)d_in[4];
  float* out = (float*)d_out;
  (void)in_sizes; (void)n_in; (void)out_size;

  dim3 b32x8(32, 8);
  k_conv<<<dim3(16, 64, 2), b32x8>>>(x, w, bias);
  k_poolrgb<<<384, 256>>>(x);
  k_kernels<<<dim3(4, 16, 2), b32x8>>>(pw);
  k_softpool<false><<<dim3(16, 16, 2), b32x8>>>(uw);
  for (int t = 0; t < 5; t++) {
    k_pac<<<dim3(8, 16, 2), dim3(16, 8)>>>();
    if (t < 4) k_softpool<true><<<dim3(16, 16, 2), b32x8>>>(uw);
    else       k_final<<<dim3(16, 16, 2), b32x8>>>(uw, out);
  }
}